// round 9
// baseline (speedup 1.0000x reference)
#include <cuda_runtime.h>
#include <cuda_bf16.h>
#include <math.h>
#include <stdint.h>

// Problem constants
#define BB 512
#define KK 256
#define NN 512
#define CC 6
#define JP (KK/2)       // 128 k-pairs
#define CHUNK 128       // tracks per block (4 blocks per batch)
#define TPB 128         // threads per block; 1 track per thread
#define NBLK (4 * BB)   // 2048

#define LOG2E_F 1.4426950408889634f
#define LN2_F   0.6931471805599453f
#define LOG2PI_LOG2E_F 2.6514961294723187f  // log2(2*pi)
#define RQ2_F 0.72134752044448170f          // 0.5 * log2(e)

// ---------------- scratch (static device globals; no allocation) -------------
__device__ double4 g_part[NBLK];             // {spatial, efs, cnt, lam} per block
__device__ unsigned int g_done = 0;

// ---------------- fast math helpers ------------------------------------------
__device__ __forceinline__ float ex2f(float x) {
    float y; asm("ex2.approx.ftz.f32 %0, %1;" : "=f"(y) : "f"(x)); return y;
}
__device__ __forceinline__ float lg2f(float x) {
    float y; asm("lg2.approx.ftz.f32 %0, %1;" : "=f"(y) : "f"(x)); return y;
}
__device__ __forceinline__ double warpRedD(double v) {
    #pragma unroll
    for (int o = 16; o; o >>= 1) v += __shfl_down_sync(0xffffffffu, v, o);
    return v;
}

// ---------------- main kernel (fully fused) -----------------------------------
__global__ __launch_bounds__(TPB, 12) void main_kernel(
    const float* __restrict__ pi,
    const float* __restrict__ mu,
    const float* __restrict__ L,
    const float* __restrict__ ef_logits,
    const float* __restrict__ tracks,
    const uint32_t* __restrict__ mask,
    float* __restrict__ out)
{
    const int bid   = blockIdx.x;
    const int b     = bid >> 2;
    const int chunk = bid & 3;
    const int tid   = threadIdx.x;

    __shared__ float4 scA[KK];         // {c0,c1,c2,c3} per k          4 KB
    __shared__ float4 scB[JP];         // {c4_k0,c5_k0,c4_k1,c5_k1}    2 KB
    __shared__ float2 sce2[JP * CC];   // {ce(2j,g), ce(2j+1,g)}       6 KB
    __shared__ double red[4 * 4];
    __shared__ bool   isLast;

    // Lambda contribution: only chunk-0 blocks accumulate pi (2 k's per thread)
    double lam = 0.0;
    if (chunk == 0) {
        lam = (double)pi[(size_t)b * KK + tid] + (double)pi[(size_t)b * KK + tid + TPB];
    }

    const int n0 = chunk * CHUNK;
    // prefix-mask property: first inactive => whole 128-track range inactive
    const bool blockActive = (mask[(size_t)b * NN + n0] != 0u);

    double spatial = 0.0, efs = 0.0, cnt = 0.0;

    if (blockActive) {
        // ---- staging (float): thread tid builds coefficients for k=tid, tid+128 ----
        #pragma unroll
        for (int kk = 0; kk < 2; kk++) {
            const int k = tid + kk * TPB;
            const int i = b * KK + k;
            float pv = pi[i];
            float a  = L[i * 4 + 0];
            float bb = L[i * 4 + 2];
            float c  = L[i * 4 + 3];
            float m0 = mu[i * 2 + 0];
            float m1 = mu[i * 2 + 1];

            float base2 = lg2f(pv) - LOG2PI_LOG2E_F - lg2f(a * c);  // < 0

            float A2  = RQ2_F / (a * a);
            float Cr2 = RQ2_F / (c * c);
            float BA  = bb / a;
            float P = fmaf(Cr2 * BA, BA, A2);
            float Q = Cr2;
            float R = -2.0f * Cr2 * BA;

            float4 v4;
            v4.x = base2 - P * m0 * m0 - Q * m1 * m1 - R * m0 * m1;
            v4.y = fmaf(2.0f * P, m0, R * m1);
            v4.z = fmaf(2.0f * Q, m1, R * m0);
            v4.w = -P;
            scA[k] = v4;

            const int j = k >> 1, lane = k & 1;
            float* fB = (float*)scB;
            fB[j * 4 + lane * 2 + 0] = -Q;
            fB[j * 4 + lane * 2 + 1] = -R;

            // CE table: lse(ef_logits) - ef_logits[c], paired layout
            float e[CC];
            float mx = -INFINITY;
            #pragma unroll
            for (int c2 = 0; c2 < CC; c2++) {
                e[c2] = ef_logits[(size_t)i * CC + c2];
                mx = fmaxf(mx, e[c2]);
            }
            float ssum = 0.f;
            #pragma unroll
            for (int c2 = 0; c2 < CC; c2++) ssum += ex2f((e[c2] - mx) * LOG2E_F);
            float lse = mx + lg2f(ssum) * LN2_F;
            float* fce = (float*)sce2;
            #pragma unroll
            for (int c2 = 0; c2 < CC; c2++) fce[(j * CC + c2) * 2 + lane] = lse - e[c2];
        }
        __syncthreads();

        // ---- per-track pass: thread tid owns track n0 + tid ----
        const int n = n0 + tid;
        const bool act = (mask[(size_t)b * NN + n] != 0u);
        if (__ballot_sync(0xffffffffu, act) != 0u) {
            // tracks memory holds finite values even where masked — safe to compute
            const float* tr = tracks + ((size_t)b * NN + n) * 6;
            const float x0 = tr[0], x1 = tr[1];
            const int   g  = (int)tr[5];
            const float xx0 = x0 * x0, xx1 = x1 * x1, x01 = x0 * x1;
            const float2* cep = sce2 + g;

            float s = 0.f, t = 0.f;
            #pragma unroll 4
            for (int j = 0; j < JP; j++) {
                float4 a0  = scA[2 * j];
                float4 a1  = scA[2 * j + 1];
                float4 bbq = scB[j];
                float2 ce  = cep[j * CC];

                float q0 = fmaf(a0.y, x0, a0.x);
                float q1 = fmaf(a1.y, x0, a1.x);
                q0 = fmaf(a0.z, x1, q0);
                q1 = fmaf(a1.z, x1, q1);
                q0 = fmaf(a0.w, xx0, q0);
                q1 = fmaf(a1.w, xx0, q1);
                q0 = fmaf(bbq.x, xx1, q0);
                q1 = fmaf(bbq.z, xx1, q1);
                q0 = fmaf(bbq.y, x01, q0);
                q1 = fmaf(bbq.w, x01, q1);

                float p0 = ex2f(q0);
                float p1 = ex2f(q1);
                s += p0;
                s += p1;
                t = fmaf(p0, ce.x, t);
                t = fmaf(p1, ce.y, t);
            }
            if (act) {
                spatial = -(double)(lg2f(s) * LN2_F);
                efs     = (double)(t / s);
                cnt     = 1.0;
            }
        }
    }

    // ---- block reduce 4 doubles (uniform control, 4 warps) ----
    spatial = warpRedD(spatial);
    efs     = warpRedD(efs);
    cnt     = warpRedD(cnt);
    lam     = warpRedD(lam);
    const int wid = tid >> 5, lid = tid & 31;
    if (lid == 0) {
        red[wid]      = spatial;
        red[4 + wid]  = efs;
        red[8 + wid]  = cnt;
        red[12 + wid] = lam;
    }
    __syncthreads();
    if (tid == 0) {
        double s0 = 0, s1 = 0, s2 = 0, s3 = 0;
        #pragma unroll
        for (int w = 0; w < 4; w++) {
            s0 += red[w]; s1 += red[4 + w]; s2 += red[8 + w]; s3 += red[12 + w];
        }
        g_part[bid] = make_double4(s0, s1, s2, s3);
    }

    // ---- last-block-done finalize (deterministic fixed-order sum) ----
    __threadfence();
    if (tid == 0) {
        unsigned int v = atomicAdd(&g_done, 1u);
        isLast = (v == (unsigned)NBLK - 1u);
    }
    __syncthreads();
    if (isLast) {
        double lamSum = 0, cntSum = 0, l1Sum = 0, spSum = 0, efSum = 0;
        for (int b2 = tid; b2 < BB; b2 += TPB) {
            double4 e0 = g_part[4 * b2];
            double4 e1 = g_part[4 * b2 + 1];
            double4 e2 = g_part[4 * b2 + 2];
            double4 e3 = g_part[4 * b2 + 3];
            double sp = (e0.x + e1.x) + (e2.x + e3.x);
            double ef = (e0.y + e1.y) + (e2.y + e3.y);
            double gc = (e0.z + e1.z) + (e2.z + e3.z);
            double lm = e0.w;  // only chunk 0 carries lam
            lamSum += lm;
            cntSum += gc;
            l1Sum  += fabs(lm - gc) * sqrt(gc + 1.0);
            spSum  += sp;
            efSum  += ef;
        }
        lamSum = warpRedD(lamSum);
        cntSum = warpRedD(cntSum);
        l1Sum  = warpRedD(l1Sum);
        spSum  = warpRedD(spSum);
        efSum  = warpRedD(efSum);
        __syncthreads();
        __shared__ double red5[4 * 5];
        if (lid == 0) {
            red5[wid]      = lamSum;
            red5[4 + wid]  = cntSum;
            red5[8 + wid]  = l1Sum;
            red5[12 + wid] = spSum;
            red5[16 + wid] = efSum;
        }
        __syncthreads();
        if (tid == 0) {
            double a0 = 0, a1 = 0, a2 = 0, a3 = 0, a4 = 0;
            #pragma unroll
            for (int w = 0; w < 4; w++) {
                a0 += red5[w]; a1 += red5[4 + w]; a2 += red5[8 + w];
                a3 += red5[12 + w]; a4 += red5[16 + w];
            }
            double count_loss = a0 / (double)BB;
            double n_total    = a1 > 1.0 ? a1 : 1.0;
            double count_l1   = a2 / (double)BB;
            double spatialL   = a3 / n_total;
            double efL        = a4 / n_total;
            double total = count_loss + spatialL + efL + count_l1;
            out[0] = (float)total;
            out[1] = (float)spatialL;
            out[2] = (float)count_loss;
            out[3] = (float)count_l1;
            out[4] = (float)efL;
            g_done = 0;  // reset for next graph replay
        }
    }
}

// ---------------- launch -------------------------------------------------------
extern "C" void kernel_launch(void* const* d_in, const int* in_sizes, int n_in,
                              void* d_out, int out_size) {
    const float* pi        = (const float*)d_in[0];
    const float* mu        = (const float*)d_in[1];
    const float* L         = (const float*)d_in[2];
    const float* ef_logits = (const float*)d_in[3];
    const float* tracks    = (const float*)d_in[4];
    const uint32_t* mask   = (const uint32_t*)d_in[5];

    main_kernel<<<NBLK, TPB>>>(pi, mu, L, ef_logits, tracks, mask, (float*)d_out);
}

// round 10
// speedup vs baseline: 1.0526x; 1.0526x over previous
#include <cuda_runtime.h>
#include <cuda_bf16.h>
#include <math.h>
#include <stdint.h>

// Problem constants
#define BB 512
#define KK 256
#define NN 512
#define CC 6
#define JP (KK/2)       // 128 k-pairs
#define HALF_N 256      // tracks per block (2 blocks per batch)
#define TPB 128         // threads per block; each thread owns 2 tracks

#define LOG2E_F 1.4426950408889634f
#define LN2_F   0.6931471805599453f
#define LOG2PI_LOG2E_F 2.6514961294723187f  // log2(2*pi)
#define RQ2_F 0.72134752044448170f          // 0.5 * log2(e)

// ---------------- scratch (static device globals; no allocation) -------------
__device__ float4 g_scA[BB * KK];        // {c0,c1,c2,c3} per (b,k)      2 MB
__device__ float4 g_scB[BB * JP];        // {c4_0,c5_0,c4_1,c5_1}        1 MB
__device__ float2 g_ce[BB * JP * CC];    // {ce(2j,g), ce(2j+1,g)}       3 MB
__device__ double4 g_part[2 * BB];       // {spatial, efs, cnt, lam}
__device__ unsigned int g_done = 0;

// ---------------- fast math helpers ------------------------------------------
__device__ __forceinline__ float ex2f(float x) {
    float y; asm("ex2.approx.ftz.f32 %0, %1;" : "=f"(y) : "f"(x)); return y;
}
__device__ __forceinline__ float lg2f(float x) {
    float y; asm("lg2.approx.ftz.f32 %0, %1;" : "=f"(y) : "f"(x)); return y;
}
__device__ __forceinline__ double warpRedD(double v) {
    #pragma unroll
    for (int o = 16; o; o >>= 1) v += __shfl_down_sync(0xffffffffu, v, o);
    return v;
}

// ---------------- kernel 1: per-(b,k) precompute (fast float) -----------------
__global__ __launch_bounds__(256) void prep_kernel(
    const float* __restrict__ pi,
    const float* __restrict__ mu,
    const float* __restrict__ L,
    const float* __restrict__ ef_logits)
{
    const int i = blockIdx.x * blockDim.x + threadIdx.x;  // (b,k) flat
    if (i >= BB * KK) return;

    float pv = pi[i];
    float a  = L[i * 4 + 0];
    float bb = L[i * 4 + 2];
    float c  = L[i * 4 + 3];
    float m0 = mu[i * 2 + 0];
    float m1 = mu[i * 2 + 1];

    float base2 = lg2f(pv) - LOG2PI_LOG2E_F - lg2f(a * c);  // < 0

    float A2  = RQ2_F / (a * a);
    float Cr2 = RQ2_F / (c * c);
    float BA  = bb / a;
    float P = fmaf(Cr2 * BA, BA, A2);
    float Q = Cr2;
    float R = -2.0f * Cr2 * BA;

    float4 v4;
    v4.x = base2 - P * m0 * m0 - Q * m1 * m1 - R * m0 * m1;
    v4.y = fmaf(2.0f * P, m0, R * m1);
    v4.z = fmaf(2.0f * Q, m1, R * m0);
    v4.w = -P;
    g_scA[i] = v4;

    const int j_glob = i >> 1, lane = i & 1;
    float* fB = (float*)g_scB;
    fB[j_glob * 4 + lane * 2 + 0] = -Q;
    fB[j_glob * 4 + lane * 2 + 1] = -R;

    // CE table: lse(ef_logits) - ef_logits[c], paired layout
    float e[CC];
    float mx = -INFINITY;
    #pragma unroll
    for (int c2 = 0; c2 < CC; c2++) {
        e[c2] = ef_logits[(size_t)i * CC + c2];
        mx = fmaxf(mx, e[c2]);
    }
    float ssum = 0.f;
    #pragma unroll
    for (int c2 = 0; c2 < CC; c2++) ssum += ex2f((e[c2] - mx) * LOG2E_F);
    float lse = mx + lg2f(ssum) * LN2_F;
    float* fce = (float*)g_ce;
    #pragma unroll
    for (int c2 = 0; c2 < CC; c2++) fce[(j_glob * CC + c2) * 2 + lane] = lse - e[c2];
}

// ---------------- kernel 2: main ------------------------------------------------
__global__ __launch_bounds__(TPB, 12) void main_kernel(
    const float* __restrict__ pi,
    const float* __restrict__ tracks,
    const uint32_t* __restrict__ mask,
    float* __restrict__ out)
{
    const int bid  = blockIdx.x;
    const int b    = bid >> 1;
    const int half = bid & 1;
    const int tid  = threadIdx.x;

    __shared__ float4 scA[KK];         // 4 KB
    __shared__ float4 scB[JP];         // 2 KB
    __shared__ float2 sce2[JP * CC];   // 6 KB
    __shared__ double red[4 * 4];
    __shared__ bool   isLast;

    // Lambda contribution: only half 0 accumulates pi (each thread covers 2 k's)
    double lam = 0.0;
    if (half == 0) {
        lam = (double)pi[(size_t)b * KK + tid] + (double)pi[(size_t)b * KK + tid + TPB];
    }

    const int n0 = half * HALF_N;
    // prefix-mask property: first inactive => whole 256-track range inactive
    const bool blockActive = (mask[(size_t)b * NN + n0] != 0u);

    double spatial = 0.0, efs = 0.0, cnt = 0.0;

    if (blockActive) {
        // ---- staging: pure bulk copy from prep output ----
        {
            const float4* gA = g_scA + (size_t)b * KK;
            scA[tid]       = gA[tid];
            scA[tid + TPB] = gA[tid + TPB];
            const float4* gB = g_scB + (size_t)b * JP;
            scB[tid] = gB[tid];
            const float4* gC = (const float4*)(g_ce + (size_t)b * JP * CC);  // 768 f2 = 384 f4
            float4* sC = (float4*)sce2;
            sC[tid]        = gC[tid];
            sC[tid + TPB]  = gC[tid + TPB];
            sC[tid + 2*TPB]= gC[tid + 2*TPB];
        }
        __syncthreads();

        // ---- per-track pass: thread owns tracks n0+tid (A) and n0+tid+128 (B) ----
        const int nA = n0 + tid;
        const int nB = nA + TPB;
        const bool actA = (mask[(size_t)b * NN + nA] != 0u);
        const bool actB = (mask[(size_t)b * NN + nB] != 0u);
        const bool anyA = (__ballot_sync(0xffffffffu, actA) != 0u);
        const bool anyB = (__ballot_sync(0xffffffffu, actB) != 0u);

        if (anyA) {
            const float* trA = tracks + ((size_t)b * NN + nA) * 6;
            const float* trB = tracks + ((size_t)b * NN + nB) * 6;
            float x0A = trA[0], x1A = trA[1];
            int   gA  = (int)trA[5];
            float xx0A = x0A * x0A, xx1A = x1A * x1A, x01A = x0A * x1A;
            const float2* cepA = sce2 + gA;

            float sA = 0.f, tA = 0.f;

            if (anyB) {
                float x0B = trB[0], x1B = trB[1];
                int   gB  = (int)trB[5];
                float xx0B = x0B * x0B, xx1B = x1B * x1B, x01B = x0B * x1B;
                const float2* cepB = sce2 + gB;
                float sB = 0.f, tB = 0.f;

                #pragma unroll 4
                for (int j = 0; j < JP; j++) {
                    float4 a0 = scA[2 * j];
                    float4 a1 = scA[2 * j + 1];
                    float4 bbq = scB[j];
                    float2 ceA = cepA[j * CC];
                    float2 ceB = cepB[j * CC];

                    float qA0 = fmaf(a0.y, x0A, a0.x);
                    float qB0 = fmaf(a0.y, x0B, a0.x);
                    float qA1 = fmaf(a1.y, x0A, a1.x);
                    float qB1 = fmaf(a1.y, x0B, a1.x);
                    qA0 = fmaf(a0.z, x1A, qA0);
                    qB0 = fmaf(a0.z, x1B, qB0);
                    qA1 = fmaf(a1.z, x1A, qA1);
                    qB1 = fmaf(a1.z, x1B, qB1);
                    qA0 = fmaf(a0.w, xx0A, qA0);
                    qB0 = fmaf(a0.w, xx0B, qB0);
                    qA1 = fmaf(a1.w, xx0A, qA1);
                    qB1 = fmaf(a1.w, xx0B, qB1);
                    qA0 = fmaf(bbq.x, xx1A, qA0);
                    qB0 = fmaf(bbq.x, xx1B, qB0);
                    qA1 = fmaf(bbq.z, xx1A, qA1);
                    qB1 = fmaf(bbq.z, xx1B, qB1);
                    qA0 = fmaf(bbq.y, x01A, qA0);
                    qB0 = fmaf(bbq.y, x01B, qB0);
                    qA1 = fmaf(bbq.w, x01A, qA1);
                    qB1 = fmaf(bbq.w, x01B, qB1);

                    float pA0 = ex2f(qA0);
                    float pB0 = ex2f(qB0);
                    float pA1 = ex2f(qA1);
                    float pB1 = ex2f(qB1);

                    sA += pA0;
                    sB += pB0;
                    sA += pA1;
                    sB += pB1;
                    tA = fmaf(pA0, ceA.x, tA);
                    tB = fmaf(pB0, ceB.x, tB);
                    tA = fmaf(pA1, ceA.y, tA);
                    tB = fmaf(pB1, ceB.y, tB);
                }
                if (actB) {
                    spatial -= (double)(lg2f(sB) * LN2_F);
                    efs     += (double)(tB / sB);
                    cnt     += 1.0;
                }
            } else {
                #pragma unroll 4
                for (int j = 0; j < JP; j++) {
                    float4 a0 = scA[2 * j];
                    float4 a1 = scA[2 * j + 1];
                    float4 bbq = scB[j];
                    float2 ceA = cepA[j * CC];

                    float qA0 = fmaf(a0.y, x0A, a0.x);
                    float qA1 = fmaf(a1.y, x0A, a1.x);
                    qA0 = fmaf(a0.z, x1A, qA0);
                    qA1 = fmaf(a1.z, x1A, qA1);
                    qA0 = fmaf(a0.w, xx0A, qA0);
                    qA1 = fmaf(a1.w, xx0A, qA1);
                    qA0 = fmaf(bbq.x, xx1A, qA0);
                    qA1 = fmaf(bbq.z, xx1A, qA1);
                    qA0 = fmaf(bbq.y, x01A, qA0);
                    qA1 = fmaf(bbq.w, x01A, qA1);

                    float pA0 = ex2f(qA0);
                    float pA1 = ex2f(qA1);
                    sA += pA0;
                    sA += pA1;
                    tA = fmaf(pA0, ceA.x, tA);
                    tA = fmaf(pA1, ceA.y, tA);
                }
            }
            if (actA) {
                spatial -= (double)(lg2f(sA) * LN2_F);
                efs     += (double)(tA / sA);
                cnt     += 1.0;
            }
        }
    }

    // ---- block reduce 4 doubles (uniform control, 4 warps) ----
    spatial = warpRedD(spatial);
    efs     = warpRedD(efs);
    cnt     = warpRedD(cnt);
    lam     = warpRedD(lam);
    const int wid = tid >> 5, lid = tid & 31;
    if (lid == 0) {
        red[wid]      = spatial;
        red[4 + wid]  = efs;
        red[8 + wid]  = cnt;
        red[12 + wid] = lam;
    }
    __syncthreads();
    if (tid == 0) {
        double s0 = 0, s1 = 0, s2 = 0, s3 = 0;
        #pragma unroll
        for (int w = 0; w < 4; w++) {
            s0 += red[w]; s1 += red[4 + w]; s2 += red[8 + w]; s3 += red[12 + w];
        }
        g_part[bid] = make_double4(s0, s1, s2, s3);
    }

    // ---- last-block-done finalize (deterministic fixed-order sum) ----
    __threadfence();
    if (tid == 0) {
        unsigned int v = atomicAdd(&g_done, 1u);
        isLast = (v == 2u * BB - 1u);
    }
    __syncthreads();
    if (isLast) {
        double lamSum = 0, cntSum = 0, l1Sum = 0, spSum = 0, efSum = 0;
        for (int b2 = tid; b2 < BB; b2 += TPB) {
            double4 e0 = g_part[2 * b2];
            double4 e1 = g_part[2 * b2 + 1];
            double sp = e0.x + e1.x;
            double ef = e0.y + e1.y;
            double gc = e0.z + e1.z;
            double lm = e0.w + e1.w;
            lamSum += lm;
            cntSum += gc;
            l1Sum  += fabs(lm - gc) * sqrt(gc + 1.0);
            spSum  += sp;
            efSum  += ef;
        }
        lamSum = warpRedD(lamSum);
        cntSum = warpRedD(cntSum);
        l1Sum  = warpRedD(l1Sum);
        spSum  = warpRedD(spSum);
        efSum  = warpRedD(efSum);
        __syncthreads();
        __shared__ double red5[4 * 5];
        if (lid == 0) {
            red5[wid]      = lamSum;
            red5[4 + wid]  = cntSum;
            red5[8 + wid]  = l1Sum;
            red5[12 + wid] = spSum;
            red5[16 + wid] = efSum;
        }
        __syncthreads();
        if (tid == 0) {
            double a0 = 0, a1 = 0, a2 = 0, a3 = 0, a4 = 0;
            #pragma unroll
            for (int w = 0; w < 4; w++) {
                a0 += red5[w]; a1 += red5[4 + w]; a2 += red5[8 + w];
                a3 += red5[12 + w]; a4 += red5[16 + w];
            }
            double count_loss = a0 / (double)BB;
            double n_total    = a1 > 1.0 ? a1 : 1.0;
            double count_l1   = a2 / (double)BB;
            double spatialL   = a3 / n_total;
            double efL        = a4 / n_total;
            double total = count_loss + spatialL + efL + count_l1;
            out[0] = (float)total;
            out[1] = (float)spatialL;
            out[2] = (float)count_loss;
            out[3] = (float)count_l1;
            out[4] = (float)efL;
            g_done = 0;  // reset for next graph replay
        }
    }
}

// ---------------- launch -------------------------------------------------------
extern "C" void kernel_launch(void* const* d_in, const int* in_sizes, int n_in,
                              void* d_out, int out_size) {
    const float* pi        = (const float*)d_in[0];
    const float* mu        = (const float*)d_in[1];
    const float* L         = (const float*)d_in[2];
    const float* ef_logits = (const float*)d_in[3];
    const float* tracks    = (const float*)d_in[4];
    const uint32_t* mask   = (const uint32_t*)d_in[5];

    prep_kernel<<<(BB * KK + 255) / 256, 256>>>(pi, mu, L, ef_logits);
    main_kernel<<<2 * BB, TPB>>>(pi, tracks, mask, (float*)d_out);
}

// round 11
// speedup vs baseline: 1.0535x; 1.0008x over previous
#include <cuda_runtime.h>
#include <cuda_bf16.h>
#include <math.h>
#include <stdint.h>

// Problem constants
#define BB 512
#define KK 256
#define NN 512
#define CC 6
#define JP (KK/2)       // 128 k-pairs
#define TPB 128         // threads per block; each thread owns 4 tracks

#define LOG2E_F 1.4426950408889634f
#define LN2_F   0.6931471805599453f
#define LOG2PI_LOG2E_F 2.6514961294723187f  // log2(2*pi)
#define RQ2_F 0.72134752044448170f          // 0.5 * log2(e)

// ---------------- scratch (static device globals; no allocation) -------------
__device__ double4 g_part[BB];           // {spatial, efs, cnt, lam} per batch
__device__ unsigned int g_done = 0;

// ---------------- fast math helpers ------------------------------------------
__device__ __forceinline__ float ex2f(float x) {
    float y; asm("ex2.approx.ftz.f32 %0, %1;" : "=f"(y) : "f"(x)); return y;
}
__device__ __forceinline__ float lg2f(float x) {
    float y; asm("lg2.approx.ftz.f32 %0, %1;" : "=f"(y) : "f"(x)); return y;
}
__device__ __forceinline__ double warpRedD(double v) {
    #pragma unroll
    for (int o = 16; o; o >>= 1) v += __shfl_down_sync(0xffffffffu, v, o);
    return v;
}

// ---------------- templated hot loop: M tracks per thread ---------------------
template <int M>
__device__ __forceinline__ void kloop(
    const float4* __restrict__ scA,
    const float4* __restrict__ scB,
    const float2* const* cep,        // per-track ce base (sce2 + g)
    const float* x0, const float* x1,
    float* s, float* t)
{
    #pragma unroll 2
    for (int j = 0; j < JP; j++) {
        const float4 a0  = scA[2 * j];
        const float4 a1  = scA[2 * j + 1];
        const float4 bbq = scB[j];
        float2 ce[M];
        #pragma unroll
        for (int m = 0; m < M; m++) ce[m] = cep[m][j * CC];

        #pragma unroll
        for (int m = 0; m < M; m++) {
            // k0:  q = c0 + (c1 + c3*x0)*x0 + (c2 + c5*x0 + c4*x1)*x1
            float u1 = fmaf(a0.w, x0[m], a0.y);
            float u2 = fmaf(bbq.y, x0[m], a0.z);
            u2 = fmaf(bbq.x, x1[m], u2);
            float q0 = fmaf(u1, x0[m], a0.x);
            q0 = fmaf(u2, x1[m], q0);
            // k1
            float v1 = fmaf(a1.w, x0[m], a1.y);
            float v2 = fmaf(bbq.w, x0[m], a1.z);
            v2 = fmaf(bbq.z, x1[m], v2);
            float q1 = fmaf(v1, x0[m], a1.x);
            q1 = fmaf(v2, x1[m], q1);

            float p0 = ex2f(q0);
            float p1 = ex2f(q1);
            s[m] += p0;
            s[m] += p1;
            t[m] = fmaf(p0, ce[m].x, t[m]);
            t[m] = fmaf(p1, ce[m].y, t[m]);
        }
    }
}

// ---------------- main kernel (fully fused, 1 block per batch) ----------------
__global__ __launch_bounds__(TPB) void main_kernel(
    const float* __restrict__ pi,
    const float* __restrict__ mu,
    const float* __restrict__ L,
    const float* __restrict__ ef_logits,
    const float* __restrict__ tracks,
    const uint32_t* __restrict__ mask,
    float* __restrict__ out)
{
    const int b   = blockIdx.x;
    const int tid = threadIdx.x;

    __shared__ float4 scA[KK];         // {c0,c1,c2,c3} per k          4 KB
    __shared__ float4 scB[JP];         // {c4_k0,c5_k0,c4_k1,c5_k1}    2 KB
    __shared__ float2 sce2[JP * CC];   // {ce(2j,g), ce(2j+1,g)}       6 KB
    __shared__ double red[4 * 4];
    __shared__ bool   isLast;

    // Lambda contribution (each thread covers 2 k's)
    double lam = (double)pi[(size_t)b * KK + tid] + (double)pi[(size_t)b * KK + tid + TPB];

    // prefix-mask property: first track inactive => whole batch empty
    const bool blockActive = (mask[(size_t)b * NN] != 0u);

    double spatial = 0.0, efs = 0.0, cnt = 0.0;

    if (blockActive) {
        // ---- staging (float): thread tid builds coefficients for k=tid, tid+128 ----
        #pragma unroll
        for (int kk = 0; kk < 2; kk++) {
            const int k = tid + kk * TPB;
            const int i = b * KK + k;
            float pv = pi[i];
            float a  = L[i * 4 + 0];
            float bb = L[i * 4 + 2];
            float c  = L[i * 4 + 3];
            float m0 = mu[i * 2 + 0];
            float m1 = mu[i * 2 + 1];

            float base2 = lg2f(pv) - LOG2PI_LOG2E_F - lg2f(a * c);  // < 0

            float A2  = RQ2_F / (a * a);
            float Cr2 = RQ2_F / (c * c);
            float BA  = bb / a;
            float P = fmaf(Cr2 * BA, BA, A2);
            float Q = Cr2;
            float R = -2.0f * Cr2 * BA;

            float4 v4;
            v4.x = base2 - P * m0 * m0 - Q * m1 * m1 - R * m0 * m1;
            v4.y = fmaf(2.0f * P, m0, R * m1);
            v4.z = fmaf(2.0f * Q, m1, R * m0);
            v4.w = -P;
            scA[k] = v4;

            const int j = k >> 1, lane = k & 1;
            float* fB = (float*)scB;
            fB[j * 4 + lane * 2 + 0] = -Q;
            fB[j * 4 + lane * 2 + 1] = -R;

            // CE table: lse(ef_logits) - ef_logits[c], paired layout
            float e[CC];
            float mx = -INFINITY;
            #pragma unroll
            for (int c2 = 0; c2 < CC; c2++) {
                e[c2] = ef_logits[(size_t)i * CC + c2];
                mx = fmaxf(mx, e[c2]);
            }
            float ssum = 0.f;
            #pragma unroll
            for (int c2 = 0; c2 < CC; c2++) ssum += ex2f((e[c2] - mx) * LOG2E_F);
            float lse = mx + lg2f(ssum) * LN2_F;
            float* fce = (float*)sce2;
            #pragma unroll
            for (int c2 = 0; c2 < CC; c2++) fce[(j * CC + c2) * 2 + lane] = lse - e[c2];
        }
        __syncthreads();

        // ---- per-track pass: thread owns tracks tid + 128*m, m=0..3 ----
        bool act[4];
        float x0[4], x1[4];
        const float2* cep[4];
        float s[4], t[4];
        int G = 0;  // number of active track-groups for this warp (prefix => contiguous)
        #pragma unroll
        for (int m = 0; m < 4; m++) {
            const int n = tid + m * TPB;
            act[m] = (mask[(size_t)b * NN + n] != 0u);
            if (__ballot_sync(0xffffffffu, act[m]) != 0u) G = m + 1;
            x0[m] = 0.f; x1[m] = 0.f;
            cep[m] = sce2;
            s[m] = 0.f; t[m] = 0.f;
        }
        #pragma unroll
        for (int m = 0; m < 4; m++) {
            if (m < G) {
                const float* tr = tracks + ((size_t)b * NN + tid + m * TPB) * 6;
                x0[m] = tr[0];
                x1[m] = tr[1];
                cep[m] = sce2 + (int)tr[5];
            }
        }

        switch (G) {
            case 4: kloop<4>(scA, scB, cep, x0, x1, s, t); break;
            case 3: kloop<3>(scA, scB, cep, x0, x1, s, t); break;
            case 2: kloop<2>(scA, scB, cep, x0, x1, s, t); break;
            case 1: kloop<1>(scA, scB, cep, x0, x1, s, t); break;
            default: break;
        }

        #pragma unroll
        for (int m = 0; m < 4; m++) {
            if (act[m]) {
                spatial -= (double)(lg2f(s[m]) * LN2_F);
                efs     += (double)(t[m] / s[m]);
                cnt     += 1.0;
            }
        }
    }

    // ---- block reduce 4 doubles (uniform control, 4 warps) ----
    spatial = warpRedD(spatial);
    efs     = warpRedD(efs);
    cnt     = warpRedD(cnt);
    lam     = warpRedD(lam);
    const int wid = tid >> 5, lid = tid & 31;
    if (lid == 0) {
        red[wid]      = spatial;
        red[4 + wid]  = efs;
        red[8 + wid]  = cnt;
        red[12 + wid] = lam;
    }
    __syncthreads();
    if (tid == 0) {
        double s0 = 0, s1 = 0, s2 = 0, s3 = 0;
        #pragma unroll
        for (int w = 0; w < 4; w++) {
            s0 += red[w]; s1 += red[4 + w]; s2 += red[8 + w]; s3 += red[12 + w];
        }
        g_part[b] = make_double4(s0, s1, s2, s3);
    }

    // ---- last-block-done finalize (deterministic fixed-order sum) ----
    __threadfence();
    if (tid == 0) {
        unsigned int v = atomicAdd(&g_done, 1u);
        isLast = (v == (unsigned)BB - 1u);
    }
    __syncthreads();
    if (isLast) {
        double lamSum = 0, cntSum = 0, l1Sum = 0, spSum = 0, efSum = 0;
        for (int b2 = tid; b2 < BB; b2 += TPB) {
            double4 e0 = g_part[b2];
            lamSum += e0.w;
            cntSum += e0.z;
            l1Sum  += fabs(e0.w - e0.z) * sqrt(e0.z + 1.0);
            spSum  += e0.x;
            efSum  += e0.y;
        }
        lamSum = warpRedD(lamSum);
        cntSum = warpRedD(cntSum);
        l1Sum  = warpRedD(l1Sum);
        spSum  = warpRedD(spSum);
        efSum  = warpRedD(efSum);
        __syncthreads();
        __shared__ double red5[4 * 5];
        if (lid == 0) {
            red5[wid]      = lamSum;
            red5[4 + wid]  = cntSum;
            red5[8 + wid]  = l1Sum;
            red5[12 + wid] = spSum;
            red5[16 + wid] = efSum;
        }
        __syncthreads();
        if (tid == 0) {
            double a0 = 0, a1 = 0, a2 = 0, a3 = 0, a4 = 0;
            #pragma unroll
            for (int w = 0; w < 4; w++) {
                a0 += red5[w]; a1 += red5[4 + w]; a2 += red5[8 + w];
                a3 += red5[12 + w]; a4 += red5[16 + w];
            }
            double count_loss = a0 / (double)BB;
            double n_total    = a1 > 1.0 ? a1 : 1.0;
            double count_l1   = a2 / (double)BB;
            double spatialL   = a3 / n_total;
            double efL        = a4 / n_total;
            double total = count_loss + spatialL + efL + count_l1;
            out[0] = (float)total;
            out[1] = (float)spatialL;
            out[2] = (float)count_loss;
            out[3] = (float)count_l1;
            out[4] = (float)efL;
            g_done = 0;  // reset for next graph replay
        }
    }
}

// ---------------- launch -------------------------------------------------------
extern "C" void kernel_launch(void* const* d_in, const int* in_sizes, int n_in,
                              void* d_out, int out_size) {
    const float* pi        = (const float*)d_in[0];
    const float* mu        = (const float*)d_in[1];
    const float* L         = (const float*)d_in[2];
    const float* ef_logits = (const float*)d_in[3];
    const float* tracks    = (const float*)d_in[4];
    const uint32_t* mask   = (const uint32_t*)d_in[5];

    main_kernel<<<BB, TPB>>>(pi, mu, L, ef_logits, tracks, mask, (float*)d_out);
}